// round 15
// baseline (speedup 1.0000x reference)
#include <cuda_runtime.h>

// SymbolSubcarrierAutocorrelation — Round 14: two-kernel split.
//   Kernel A: stages 1+2 (4 column-pairs/thread, five single-s passes -> 16-float
//             accumulators, no spills). Writes folded E/D + P0 to 52MB device scratch.
//   Kernel B: stages 3+4. Zero smem, zero barriers: LDG (L1/L2-hot) + FMA + STG.
//   Rationale: R12/R13 proved 4-pair consumers cut L1, but stage2+stage3 registers
//   can't coexist in one kernel (R13 spilled at 128 regs, occ ceiling 25%).

#define SDIM 5
#define WDIM 33
#define ADIM 16
#define NPAIR 16
#define TPB 32
#define PAIRT (TPB * 4)          // 128 pair-threads
#define THREADS 160              // +32 v0-threads
#define MAXTILES 65536
#define EDSTRIDE 200             // floats/tile: 16w x 12 (E0..3|D0..3|E4,D4,pad) + P0[5] + pad3

__device__ __align__(16) float g_ed[(size_t)MAXTILES * EDSTRIDE];   // ~52 MB scratch

// ---------------- Kernel A: stages 1 + 2 ----------------
__global__ __launch_bounds__(THREADS, 5)
void autocorrA_kernel(const float* __restrict__ xr, const float* __restrict__ xi,
                      const float* __restrict__ fsA, const float* __restrict__ fsB,
                      const float* __restrict__ fwA, const float* __restrict__ fwB,
                      int total_tiles, unsigned int xcount)
{
    __shared__ float4 sSD [TPB * NPAIR * SDIM];     // 40960 B (Sr,Si,Dr,Di)
    __shared__ float2 sT10[TPB][SDIM];              //  1280 B

    const int tid = threadIdx.x;

    const bool swSub = (fabsf(fwA[0]) < 1e-3f);
    const bool swSym = (fabsf(fsA[0]) < 1e-3f);
    const float* __restrict__ fwr = swSub ? fwB : fwA;
    const float* __restrict__ fwi = swSub ? fwA : fwB;
    const float* __restrict__ fsr = swSym ? fsB : fsA;
    const float* __restrict__ fsi = swSym ? fsA : fsB;

    const float k = fwr[0];                         // 1/sqrt(33)
    const float invk = 1.0f / k;

    float zr[SDIM], zi[SDIM];                       // F_sym[s][t] = z[(s*t)%5]
    #pragma unroll
    for (int q2 = 0; q2 < SDIM; q2++) { zr[q2] = fsr[SDIM + q2]; zi[q2] = fsi[SDIM + q2]; }

    const bool isV0 = (tid >= PAIRT);
    int ts, q;
    if (isV0) { ts = tid - PAIRT; q = 0; }
    else      { ts = tid >> 2;    q = tid & 3; }
    int tile = blockIdx.x * TPB + ts;
    if (tile >= total_tiles) tile = 0;
    if (tile >= MAXTILES) tile = 0;
    const int n = tile >> 4;                        // ADIM == 16
    const int a = tile & 15;
    const unsigned int rowbase0 = (((unsigned int)n * SDIM) * ADIM + a) * WDIM;
    float* const edBase = g_ed + (size_t)tile * EDSTRIDE;

    float2 u1[4], ra[4];
    if (!isV0) {
        #pragma unroll
        for (int p = 0; p < 4; p++) {
            const int c = 4 * q + 1 + p;
            u1[p] = make_float2(fwr[WDIM + c], fwi[WDIM + c]);
            ra[p] = make_float2(u1[p].x * invk, u1[p].y * invk);
        }
    }

    float t10v[2 * SDIM];
    // ---- Stage 1 ----
    if (!isV0) {
        #pragma unroll
        for (int p = 0; p < 4; p++) {
            const int v = 4 * q + 1 + p;
            const int vm = WDIM - v;
            float2 xa[SDIM], xb[SDIM];
            #pragma unroll
            for (int t = 0; t < SDIM; t++) {
                unsigned int base = rowbase0 + (unsigned int)t * (ADIM * WDIM);
                unsigned int iA = base + v;  if (iA >= xcount) iA = 0;
                unsigned int iB = base + vm; if (iB >= xcount) iB = 0;
                xa[t] = make_float2(xr[iA], xi[iA]);
                xb[t] = make_float2(xr[iB], xi[iB]);
            }
            #pragma unroll
            for (int s = 0; s < SDIM; s++) {
                float Ar = 0.f, Ai = 0.f, Br = 0.f, Bi = 0.f;
                #pragma unroll
                for (int t = 0; t < SDIM; t++) {
                    const int I = (s * t) % SDIM;
                    const float cr = zr[I], ci = zi[I];
                    Ar += cr * xa[t].x - ci * xa[t].y;
                    Ai += cr * xa[t].y + ci * xa[t].x;
                    Br += cr * xb[t].x - ci * xb[t].y;
                    Bi += cr * xb[t].y + ci * xb[t].x;
                }
                sSD[(ts * NPAIR + (v - 1)) * SDIM + s] =
                    make_float4(Ar + Br, Ai + Bi, Ar - Br, Ai - Bi);
            }
        }
    } else {
        float2 x0[SDIM];
        #pragma unroll
        for (int t = 0; t < SDIM; t++) {
            unsigned int iA = rowbase0 + (unsigned int)t * (ADIM * WDIM);
            if (iA >= xcount) iA = 0;
            x0[t] = make_float2(xr[iA], xi[iA]);
        }
        #pragma unroll
        for (int s = 0; s < SDIM; s++) {
            float Ar = 0.f, Ai = 0.f;
            #pragma unroll
            for (int t = 0; t < SDIM; t++) {
                const int I = (s * t) % SDIM;
                Ar += zr[I] * x0[t].x - zi[I] * x0[t].y;
                Ai += zr[I] * x0[t].y + zi[I] * x0[t].x;
            }
            t10v[2 * s] = Ar; t10v[2 * s + 1] = Ai;
            sT10[ts][s] = make_float2(Ar, Ai);
        }
    }
    __syncthreads();

    // ---- Stage 2: five single-s passes (16-float accumulators) ----
    if (!isV0) {
        const float4* const sdTile = &sSD[ts * NPAIR * SDIM];
        #pragma unroll
        for (int s = 0; s < SDIM; s++) {
            const float2 t10 = sT10[ts][s];
            const float br = k * t10.x, bi = k * t10.y;
            float Xr[4][2], Xi[4][2];
            #pragma unroll
            for (int p = 0; p < 4; p++) {
                Xr[p][0] = br; Xr[p][1] = br;
                Xi[p][0] = bi; Xi[p][1] = bi;
            }
            float2 fa[4];
            #pragma unroll
            for (int p = 0; p < 4; p++) fa[p] = u1[p];
            #pragma unroll 4
            for (int w = 0; w < NPAIR; w++) {
                const float4 sd = sdTile[w * SDIM + s];
                #pragma unroll
                for (int p = 0; p < 4; p++) {
                    const float c = fa[p].x, si = fa[p].y;
                    const float pa = c * sd.x, pb = si * sd.w;
                    const float pc_ = c * sd.y, pd = si * sd.z;
                    Xr[p][0] += pa - pb;  Xi[p][0] += pc_ + pd;
                    Xr[p][1] += pa + pb;  Xi[p][1] += pc_ - pd;
                    fa[p] = make_float2(fa[p].x * ra[p].x - fa[p].y * ra[p].y,
                                        fa[p].x * ra[p].y + fa[p].y * ra[p].x);
                }
            }
            const int eo = (s < 4) ? s     : 8;
            const int dn = (s < 4) ? 4 + s : 9;
            #pragma unroll
            for (int p = 0; p < 4; p++) {
                const float Pv = Xr[p][0]*Xr[p][0] + Xi[p][0]*Xi[p][0];
                const float Pm = Xr[p][1]*Xr[p][1] + Xi[p][1]*Xi[p][1];
                const int wp = 4 * q + p;
                edBase[wp * 12 + eo] = Pv + Pm;
                edBase[wp * 12 + dn] = Pv - Pm;
            }
        }
    } else {
        float sr[SDIM] = {0,0,0,0,0}, sm[SDIM] = {0,0,0,0,0};
        #pragma unroll 4
        for (int w = 0; w < NPAIR; w++) {
            #pragma unroll
            for (int s = 0; s < SDIM; s++) {
                const float2 sv = *reinterpret_cast<const float2*>(
                    &sSD[(ts * NPAIR + w) * SDIM + s]);
                sr[s] += sv.x;  sm[s] += sv.y;
            }
        }
        #pragma unroll
        for (int s = 0; s < SDIM; s++) {
            const float X0r = k * (t10v[2 * s]     + sr[s]);
            const float X0i = k * (t10v[2 * s + 1] + sm[s]);
            edBase[192 + s] = X0r * X0r + X0i * X0i;     // P0
        }
    }
}

// ---------------- Kernel B: stages 3 + 4 (no smem, no barriers) ----------------
__global__ __launch_bounds__(THREADS, 4)
void autocorrB_kernel(const float* __restrict__ fsA, const float* __restrict__ fsB,
                      const float* __restrict__ fwA, const float* __restrict__ fwB,
                      float* __restrict__ outf,
                      int total_tiles, unsigned int out_limit, int real_only)
{
    const int tid = threadIdx.x;

    const bool swSub = (fabsf(fwA[0]) < 1e-3f);
    const bool swSym = (fabsf(fsA[0]) < 1e-3f);
    const float* __restrict__ fwr = swSub ? fwB : fwA;
    const float* __restrict__ fwi = swSub ? fwA : fwB;
    const float* __restrict__ fsr = swSym ? fsB : fsA;
    const float* __restrict__ fsi = swSym ? fsA : fsB;

    const float k = fwr[0];
    const float invk = 1.0f / k;

    float zr[SDIM], zi[SDIM];
    #pragma unroll
    for (int q2 = 0; q2 < SDIM; q2++) { zr[q2] = fsr[SDIM + q2]; zi[q2] = fsi[SDIM + q2]; }

    const bool isV0 = (tid >= PAIRT);
    int ts, q;
    if (isV0) { ts = tid - PAIRT; q = 0; }
    else      { ts = tid >> 2;    q = tid & 3; }
    int tile = blockIdx.x * TPB + ts;
    if (tile >= total_tiles) tile = 0;
    if (tile >= MAXTILES) tile = 0;
    const int n = tile >> 4;
    const int a = tile & 15;
    const float* const edBase = g_ed + (size_t)tile * EDSTRIDE;

    float p0[SDIM];
    #pragma unroll
    for (int s = 0; s < SDIM; s++) p0[s] = __ldg(edBase + 192 + s);

    if (!isV0) {
        float2 u1[4], ra[4];
        #pragma unroll
        for (int p = 0; p < 4; p++) {
            const int c = 4 * q + 1 + p;
            u1[p] = make_float2(fwr[WDIM + c], fwi[WDIM + c]);
            ra[p] = make_float2(u1[p].x * invk, u1[p].y * invk);
        }
        float t2r[4][SDIM], t2i[4][SDIM];
        #pragma unroll
        for (int s = 0; s < SDIM; s++) {
            const float b = k * p0[s];
            #pragma unroll
            for (int p = 0; p < 4; p++) { t2r[p][s] = b; t2i[p][s] = 0.f; }
        }
        float2 fa[4];
        #pragma unroll
        for (int p = 0; p < 4; p++) fa[p] = u1[p];
        #pragma unroll 4
        for (int w = 0; w < NPAIR; w++) {
            const float4 E4 = __ldg(reinterpret_cast<const float4*>(edBase + w * 12));
            const float4 D4 = __ldg(reinterpret_cast<const float4*>(edBase + w * 12 + 4));
            const float2 eD = __ldg(reinterpret_cast<const float2*>(edBase + w * 12 + 8));
            #pragma unroll
            for (int p = 0; p < 4; p++) {
                const float c = fa[p].x, si = fa[p].y;
                t2r[p][0] += E4.x * c;  t2i[p][0] -= D4.x * si;
                t2r[p][1] += E4.y * c;  t2i[p][1] -= D4.y * si;
                t2r[p][2] += E4.z * c;  t2i[p][2] -= D4.z * si;
                t2r[p][3] += E4.w * c;  t2i[p][3] -= D4.w * si;
                t2r[p][4] += eD.x * c;  t2i[p][4] -= eD.y * si;
                fa[p] = make_float2(fa[p].x * ra[p].x - fa[p].y * ra[p].y,
                                    fa[p].x * ra[p].y + fa[p].y * ra[p].x);
            }
        }
        #pragma unroll
        for (int p = 0; p < 4; p++) {
            const int v = 4 * q + 1 + p;
            #pragma unroll
            for (int sp = 0; sp < SDIM; sp++) {
                float yr = 0.f, yi = 0.f;
                #pragma unroll
                for (int s = 0; s < SDIM; s++) {
                    const int I = (s * sp) % SDIM;
                    yr += zr[I] * t2r[p][s] + zi[I] * t2i[p][s];
                    yi += zr[I] * t2i[p][s] - zi[I] * t2r[p][s];
                }
                unsigned int oidx = (((unsigned int)n * SDIM + sp) * ADIM + a) * WDIM + v;
                const int sp2 = (SDIM - sp) % SDIM;
                unsigned int midx = (((unsigned int)n * SDIM + sp2) * ADIM + a) * WDIM + (WDIM - v);
                if (real_only) {
                    if (oidx < out_limit) outf[oidx] = yr;
                    if (midx < out_limit) outf[midx] = yr;
                } else {
                    if (2u * oidx + 1u < out_limit)
                        reinterpret_cast<float2*>(outf)[oidx] = make_float2(yr, yi);
                    if (2u * midx + 1u < out_limit)
                        reinterpret_cast<float2*>(outf)[midx] = make_float2(yr, -yi);
                }
            }
        }
    } else {
        float accE[SDIM] = {0,0,0,0,0};
        #pragma unroll 4
        for (int w = 0; w < NPAIR; w++) {
            const float4 E4 = __ldg(reinterpret_cast<const float4*>(edBase + w * 12));
            const float2 eD = __ldg(reinterpret_cast<const float2*>(edBase + w * 12 + 8));
            accE[0] += E4.x; accE[1] += E4.y; accE[2] += E4.z; accE[3] += E4.w;
            accE[4] += eD.x;
        }
        float t2r0[SDIM];
        #pragma unroll
        for (int s = 0; s < SDIM; s++)
            t2r0[s] = k * (p0[s] + accE[s]);
        #pragma unroll
        for (int sp = 0; sp < SDIM; sp++) {
            float yr = 0.f, yi = 0.f;
            #pragma unroll
            for (int s = 0; s < SDIM; s++) {
                const int I = (s * sp) % SDIM;
                yr += zr[I] * t2r0[s];
                yi -= zi[I] * t2r0[s];
            }
            unsigned int oidx = (((unsigned int)n * SDIM + sp) * ADIM + a) * WDIM;
            if (real_only) {
                if (oidx < out_limit) outf[oidx] = yr;
            } else {
                if (2u * oidx + 1u < out_limit)
                    reinterpret_cast<float2*>(outf)[oidx] = make_float2(yr, yi);
            }
        }
    }
}

extern "C" void kernel_launch(void* const* d_in, const int* in_sizes, int n_in,
                              void* d_out, int out_size)
{
    long long big_raw = -1;
    for (int i = 0; i < n_in; i++)
        if ((long long)in_sizes[i] > big_raw) big_raw = in_sizes[i];

    const float *xr = 0, *xi = 0, *fsA = 0, *fsB = 0, *fwA = 0, *fwB = 0;
    int nsym = 0, nsub = 0, nbig = 0;
    for (int i = 0; i < n_in; i++) {
        const float* p = (const float*)d_in[i];
        long long c = in_sizes[i];
        if (c == SDIM * SDIM) {
            if (nsym++ == 0) fsA = p; else if (!fsB) fsB = p;
        } else if (c == WDIM * WDIM) {
            if (nsub++ == 0) fwA = p; else if (!fwB) fwB = p;
        } else if (c == big_raw) {
            if (nbig++ == 0) xr = p; else if (!xi) xi = p;
        }
    }
    if (!xr || !xi || !fsA || !fsB || !fwA || !fwB) return;

    const long long C = big_raw;
    const int N = (int)(C / (SDIM * ADIM * WDIM));
    const int total_tiles = N * ADIM;
    if (total_tiles <= 0) return;
    const int blocks = (total_tiles + TPB - 1) / TPB;

    const int real_only = ((long long)out_size >= 2 * C) ? 0 : 1;

    autocorrA_kernel<<<blocks, THREADS>>>(
        xr, xi, fsA, fsB, fwA, fwB, total_tiles, (unsigned int)C);
    autocorrB_kernel<<<blocks, THREADS>>>(
        fsA, fsB, fwA, fwB, (float*)d_out, total_tiles,
        (unsigned int)out_size, real_only);
}

// round 16
// speedup vs baseline: 1.5098x; 1.5098x over previous
#include <cuda_runtime.h>

// SymbolSubcarrierAutocorrelation — Round 16: per-stage role remap, all-smem exchange.
//   Stage 1: 8 thr/tile (2 pairs each)   [tid 0..127], v0 [128..143]
//   Stage 2: 4 thr/tile (4 pairs each), PACKED warps [tid 0..63], v0 [64..79]
//            five single-s passes (16 accums, no spills), E/D -> smem
//   Stage 3+4: 8 thr/tile (2 pairs each) [tid 0..127], v0 [128..143]
//   Packing stage-2 consumers into whole warps halves sd smem delivery without
//   increasing FMA warp-instructions (the R12-R15 global-scratch detour is dead).

#define SDIM 5
#define WDIM 33
#define ADIM 16
#define NPAIR 16
#define TPB 16
#define THREADS 160

__global__ __launch_bounds__(THREADS, 6)
void autocorr_kernel(const float* __restrict__ xr, const float* __restrict__ xi,
                     const float* __restrict__ fsA, const float* __restrict__ fsB,
                     const float* __restrict__ fwA, const float* __restrict__ fwB,
                     float* __restrict__ outf,
                     int total_tiles,
                     unsigned int xcount,
                     unsigned int out_limit,
                     int real_only)
{
    __shared__ float4 sSD [TPB * NPAIR * SDIM];     // 20480 B (Sr,Si,Dr,Di)
    __shared__ float4 sEDa[TPB * NPAIR];            //  4096 B E0..3
    __shared__ float4 sEDb[TPB * NPAIR];            //  4096 B D0..3
    __shared__ float2 sEDc[TPB * NPAIR];            //  2048 B (E4,D4)
    __shared__ float2 sT10[TPB][SDIM];              //   640 B
    __shared__ float  sP0 [TPB][SDIM];              //   320 B  => 31680 B

    const int tid = threadIdx.x;

    const bool swSub = (fabsf(fwA[0]) < 1e-3f);
    const bool swSym = (fabsf(fsA[0]) < 1e-3f);
    const float* __restrict__ fwr = swSub ? fwB : fwA;
    const float* __restrict__ fwi = swSub ? fwA : fwB;
    const float* __restrict__ fsr = swSym ? fsB : fsA;
    const float* __restrict__ fsi = swSym ? fsA : fsB;

    const float k = fwr[0];                         // 1/sqrt(33)
    const float invk = 1.0f / k;

    float zr[SDIM], zi[SDIM];                       // F_sym[s][t] = z[(s*t)%5]
    #pragma unroll
    for (int q2 = 0; q2 < SDIM; q2++) { zr[q2] = fsr[SDIM + q2]; zi[q2] = fsi[SDIM + q2]; }

    // ================= Stage 1: 8 thr/tile, 2 pairs each =================
    if (tid < 8 * TPB) {
        const int ts = tid >> 3, j = tid & 7;
        int tile = blockIdx.x * TPB + ts;
        if (tile >= total_tiles) tile = 0;
        const int n = tile >> 4, a = tile & 15;
        const unsigned int rowbase0 = (((unsigned int)n * SDIM) * ADIM + a) * WDIM;
        #pragma unroll
        for (int pc = 0; pc < 2; pc++) {
            const int v = 2 * j + 1 + pc;
            const int vm = WDIM - v;
            float2 xa[SDIM], xb[SDIM];
            #pragma unroll
            for (int t = 0; t < SDIM; t++) {
                unsigned int base = rowbase0 + (unsigned int)t * (ADIM * WDIM);
                unsigned int iA = base + v;  if (iA >= xcount) iA = 0;
                unsigned int iB = base + vm; if (iB >= xcount) iB = 0;
                xa[t] = make_float2(xr[iA], xi[iA]);
                xb[t] = make_float2(xr[iB], xi[iB]);
            }
            #pragma unroll
            for (int s = 0; s < SDIM; s++) {
                float Ar = 0.f, Ai = 0.f, Br = 0.f, Bi = 0.f;
                #pragma unroll
                for (int t = 0; t < SDIM; t++) {
                    const int I = (s * t) % SDIM;
                    const float cr = zr[I], ci = zi[I];
                    Ar += cr * xa[t].x - ci * xa[t].y;
                    Ai += cr * xa[t].y + ci * xa[t].x;
                    Br += cr * xb[t].x - ci * xb[t].y;
                    Bi += cr * xb[t].y + ci * xb[t].x;
                }
                sSD[(ts * NPAIR + (v - 1)) * SDIM + s] =
                    make_float4(Ar + Br, Ai + Bi, Ar - Br, Ai - Bi);
            }
        }
    } else if (tid < 8 * TPB + TPB) {               // v0: T1[s][0]
        const int ts = tid - 8 * TPB;
        int tile = blockIdx.x * TPB + ts;
        if (tile >= total_tiles) tile = 0;
        const int n = tile >> 4, a = tile & 15;
        const unsigned int rowbase0 = (((unsigned int)n * SDIM) * ADIM + a) * WDIM;
        float2 x0[SDIM];
        #pragma unroll
        for (int t = 0; t < SDIM; t++) {
            unsigned int iA = rowbase0 + (unsigned int)t * (ADIM * WDIM);
            if (iA >= xcount) iA = 0;
            x0[t] = make_float2(xr[iA], xi[iA]);
        }
        #pragma unroll
        for (int s = 0; s < SDIM; s++) {
            float Ar = 0.f, Ai = 0.f;
            #pragma unroll
            for (int t = 0; t < SDIM; t++) {
                const int I = (s * t) % SDIM;
                Ar += zr[I] * x0[t].x - zi[I] * x0[t].y;
                Ai += zr[I] * x0[t].y + zi[I] * x0[t].x;
            }
            sT10[ts][s] = make_float2(Ar, Ai);
        }
    }
    __syncthreads();

    // ================= Stage 2: 4 thr/tile (packed warps), 4 pairs each =================
    if (tid < 4 * TPB) {
        const int ts = tid >> 2, q = tid & 3;
        float2 u1[4], ra[4];
        #pragma unroll
        for (int p = 0; p < 4; p++) {
            const int c = 4 * q + 1 + p;
            u1[p] = make_float2(fwr[WDIM + c], fwi[WDIM + c]);
            ra[p] = make_float2(u1[p].x * invk, u1[p].y * invk);
        }
        #pragma unroll
        for (int s = 0; s < SDIM; s++) {
            const float2 t10 = sT10[ts][s];
            const float br = k * t10.x, bi = k * t10.y;
            float Xr[4][2], Xi[4][2];
            #pragma unroll
            for (int p = 0; p < 4; p++) {
                Xr[p][0] = br; Xr[p][1] = br;
                Xi[p][0] = bi; Xi[p][1] = bi;
            }
            float2 fa[4];
            #pragma unroll
            for (int p = 0; p < 4; p++) fa[p] = u1[p];
            #pragma unroll 4
            for (int w = 0; w < NPAIR; w++) {
                const float4 sd = sSD[(ts * NPAIR + w) * SDIM + s];
                #pragma unroll
                for (int p = 0; p < 4; p++) {
                    const float c = fa[p].x, si = fa[p].y;
                    const float pa = c * sd.x, pb = si * sd.w;
                    const float pc_ = c * sd.y, pd = si * sd.z;
                    Xr[p][0] += pa - pb;  Xi[p][0] += pc_ + pd;
                    Xr[p][1] += pa + pb;  Xi[p][1] += pc_ - pd;
                    fa[p] = make_float2(fa[p].x * ra[p].x - fa[p].y * ra[p].y,
                                        fa[p].x * ra[p].y + fa[p].y * ra[p].x);
                }
            }
            #pragma unroll
            for (int p = 0; p < 4; p++) {
                const float Pv = Xr[p][0]*Xr[p][0] + Xi[p][0]*Xi[p][0];
                const float Pm = Xr[p][1]*Xr[p][1] + Xi[p][1]*Xi[p][1];
                const int wp = ts * NPAIR + 4 * q + p;
                if (s < 4) {
                    reinterpret_cast<float*>(&sEDa[wp])[s] = Pv + Pm;
                    reinterpret_cast<float*>(&sEDb[wp])[s] = Pv - Pm;
                } else {
                    sEDc[wp] = make_float2(Pv + Pm, Pv - Pm);
                }
            }
        }
    } else if (tid < 4 * TPB + TPB) {               // v0: P0[s]
        const int ts = tid - 4 * TPB;
        float sr[SDIM] = {0,0,0,0,0}, sm[SDIM] = {0,0,0,0,0};
        #pragma unroll 4
        for (int w = 0; w < NPAIR; w++) {
            #pragma unroll
            for (int s = 0; s < SDIM; s++) {
                const float2 sv = *reinterpret_cast<const float2*>(
                    &sSD[(ts * NPAIR + w) * SDIM + s]);
                sr[s] += sv.x;  sm[s] += sv.y;
            }
        }
        #pragma unroll
        for (int s = 0; s < SDIM; s++) {
            const float2 t10 = sT10[ts][s];
            const float X0r = k * (t10.x + sr[s]);
            const float X0i = k * (t10.y + sm[s]);
            sP0[ts][s] = X0r * X0r + X0i * X0i;
        }
    }
    __syncthreads();

    // ================= Stages 3 + 4: 8 thr/tile, 2 pairs each =================
    if (tid < 8 * TPB) {
        const int ts = tid >> 3, j = tid & 7;
        int tile = blockIdx.x * TPB + ts;
        if (tile >= total_tiles) tile = 0;
        const int n = tile >> 4, a = tile & 15;
        const int c1 = 2 * j + 1, c2 = 2 * j + 2;
        const float2 u1a = make_float2(fwr[WDIM + c1], fwi[WDIM + c1]);
        const float2 u1b = make_float2(fwr[WDIM + c2], fwi[WDIM + c2]);
        const float2 rA = make_float2(u1a.x * invk, u1a.y * invk);
        const float2 rB = make_float2(u1b.x * invk, u1b.y * invk);

        float t2r[2][SDIM], t2i[2][SDIM];
        #pragma unroll
        for (int s = 0; s < SDIM; s++) {
            const float b = k * sP0[ts][s];
            t2r[0][s] = b; t2r[1][s] = b;
            t2i[0][s] = 0.f; t2i[1][s] = 0.f;
        }
        float2 fa = u1a, fb = u1b;
        #pragma unroll 4
        for (int w = 0; w < NPAIR; w++) {
            const float4 E4 = sEDa[ts * NPAIR + w];
            const float4 D4 = sEDb[ts * NPAIR + w];
            const float2 eD = sEDc[ts * NPAIR + w];
            t2r[0][0] += E4.x * fa.x;  t2i[0][0] -= D4.x * fa.y;
            t2r[0][1] += E4.y * fa.x;  t2i[0][1] -= D4.y * fa.y;
            t2r[0][2] += E4.z * fa.x;  t2i[0][2] -= D4.z * fa.y;
            t2r[0][3] += E4.w * fa.x;  t2i[0][3] -= D4.w * fa.y;
            t2r[0][4] += eD.x * fa.x;  t2i[0][4] -= eD.y * fa.y;
            t2r[1][0] += E4.x * fb.x;  t2i[1][0] -= D4.x * fb.y;
            t2r[1][1] += E4.y * fb.x;  t2i[1][1] -= D4.y * fb.y;
            t2r[1][2] += E4.z * fb.x;  t2i[1][2] -= D4.z * fb.y;
            t2r[1][3] += E4.w * fb.x;  t2i[1][3] -= D4.w * fb.y;
            t2r[1][4] += eD.x * fb.x;  t2i[1][4] -= eD.y * fb.y;
            fa = make_float2(fa.x * rA.x - fa.y * rA.y, fa.x * rA.y + fa.y * rA.x);
            fb = make_float2(fb.x * rB.x - fb.y * rB.y, fb.x * rB.y + fb.y * rB.x);
        }
        #pragma unroll
        for (int pc = 0; pc < 2; pc++) {
            const int v = 2 * j + 1 + pc;
            #pragma unroll
            for (int sp = 0; sp < SDIM; sp++) {
                float yr = 0.f, yi = 0.f;
                #pragma unroll
                for (int s = 0; s < SDIM; s++) {
                    const int I = (s * sp) % SDIM;
                    yr += zr[I] * t2r[pc][s] + zi[I] * t2i[pc][s];
                    yi += zr[I] * t2i[pc][s] - zi[I] * t2r[pc][s];
                }
                unsigned int oidx = (((unsigned int)n * SDIM + sp) * ADIM + a) * WDIM + v;
                const int sp2 = (SDIM - sp) % SDIM;
                unsigned int midx = (((unsigned int)n * SDIM + sp2) * ADIM + a) * WDIM + (WDIM - v);
                if (real_only) {
                    if (oidx < out_limit) outf[oidx] = yr;
                    if (midx < out_limit) outf[midx] = yr;
                } else {
                    if (2u * oidx + 1u < out_limit)
                        reinterpret_cast<float2*>(outf)[oidx] = make_float2(yr, yi);
                    if (2u * midx + 1u < out_limit)
                        reinterpret_cast<float2*>(outf)[midx] = make_float2(yr, -yi);
                }
            }
        }
    } else if (tid < 8 * TPB + TPB) {               // v0 outputs
        const int ts = tid - 8 * TPB;
        int tile = blockIdx.x * TPB + ts;
        if (tile >= total_tiles) tile = 0;
        const int n = tile >> 4, a = tile & 15;
        float accE[SDIM] = {0,0,0,0,0};
        #pragma unroll 4
        for (int w = 0; w < NPAIR; w++) {
            const float4 E4 = sEDa[ts * NPAIR + w];
            const float2 eD = sEDc[ts * NPAIR + w];
            accE[0] += E4.x; accE[1] += E4.y; accE[2] += E4.z; accE[3] += E4.w;
            accE[4] += eD.x;
        }
        float t2r0[SDIM];
        #pragma unroll
        for (int s = 0; s < SDIM; s++)
            t2r0[s] = k * (sP0[ts][s] + accE[s]);
        #pragma unroll
        for (int sp = 0; sp < SDIM; sp++) {
            float yr = 0.f, yi = 0.f;
            #pragma unroll
            for (int s = 0; s < SDIM; s++) {
                const int I = (s * sp) % SDIM;
                yr += zr[I] * t2r0[s];
                yi -= zi[I] * t2r0[s];
            }
            unsigned int oidx = (((unsigned int)n * SDIM + sp) * ADIM + a) * WDIM;
            if (real_only) {
                if (oidx < out_limit) outf[oidx] = yr;
            } else {
                if (2u * oidx + 1u < out_limit)
                    reinterpret_cast<float2*>(outf)[oidx] = make_float2(yr, yi);
            }
        }
    }
}

extern "C" void kernel_launch(void* const* d_in, const int* in_sizes, int n_in,
                              void* d_out, int out_size)
{
    long long big_raw = -1;
    for (int i = 0; i < n_in; i++)
        if ((long long)in_sizes[i] > big_raw) big_raw = in_sizes[i];

    const float *xr = 0, *xi = 0, *fsA = 0, *fsB = 0, *fwA = 0, *fwB = 0;
    int nsym = 0, nsub = 0, nbig = 0;
    for (int i = 0; i < n_in; i++) {
        const float* p = (const float*)d_in[i];
        long long c = in_sizes[i];
        if (c == SDIM * SDIM) {
            if (nsym++ == 0) fsA = p; else if (!fsB) fsB = p;
        } else if (c == WDIM * WDIM) {
            if (nsub++ == 0) fwA = p; else if (!fwB) fwB = p;
        } else if (c == big_raw) {
            if (nbig++ == 0) xr = p; else if (!xi) xi = p;
        }
    }
    if (!xr || !xi || !fsA || !fsB || !fwA || !fwB) return;

    const long long C = big_raw;
    const int N = (int)(C / (SDIM * ADIM * WDIM));
    const int total_tiles = N * ADIM;
    if (total_tiles <= 0) return;
    const int blocks = (total_tiles + TPB - 1) / TPB;

    const int real_only = ((long long)out_size >= 2 * C) ? 0 : 1;

    autocorr_kernel<<<blocks, THREADS>>>(
        xr, xi, fsA, fsB, fwA, fwB, (float*)d_out, total_tiles,
        (unsigned int)C, (unsigned int)out_size, real_only);
}

// round 17
// speedup vs baseline: 1.6977x; 1.1244x over previous
#include <cuda_runtime.h>

// SymbolSubcarrierAutocorrelation — Round 17: R11 structure + coalesced stage-1.
//   * Stage 1: thread j loads columns {j, j+8, j+16, j+24} (warp-coalesced 32B runs),
//     writes UNFOLDED T1 to smem (s-major float2 layout, conflict-free half-warps).
//   * Stage 2: fold on the read side (Ta=T1[w], Tb=T1[33-w]); u/v product sharing
//     keeps FMA ops identical to R11's folded form. Twiddle recurrence kept.
//   * Stage 3+4 and ED exchange: verbatim R11 (best known: 90.6us).

#define SDIM 5
#define WDIM 33
#define ADIM 16
#define NPAIR 16
#define TPB 16
#define PAIRT (TPB * 8)         // 128 pair-threads
#define THREADS 160             // + 16 v0-threads + 16 idle

__global__ __launch_bounds__(THREADS, 6)
void autocorr_kernel(const float* __restrict__ xr, const float* __restrict__ xi,
                     const float* __restrict__ fsA, const float* __restrict__ fsB,
                     const float* __restrict__ fwA, const float* __restrict__ fwB,
                     float* __restrict__ outf,
                     int total_tiles,
                     unsigned int xcount,
                     unsigned int out_limit,
                     int real_only)
{
    __shared__ float2 sT1 [TPB][SDIM][WDIM];    // 21120 B  unfolded T1 (s-major)
    __shared__ float4 sEDa[TPB * NPAIR];        //  4096 B  E0..3
    __shared__ float4 sEDb[TPB * NPAIR];        //  4096 B  D0..3
    __shared__ float2 sEDc[TPB * NPAIR];        //  2048 B  (E4,D4)
    __shared__ float  sP0 [TPB][SDIM];          //   320 B  => 31680 B

    const int tid = threadIdx.x;

    const bool swSub = (fabsf(fwA[0]) < 1e-3f);
    const bool swSym = (fabsf(fsA[0]) < 1e-3f);
    const float* __restrict__ fwr = swSub ? fwB : fwA;
    const float* __restrict__ fwi = swSub ? fwA : fwB;
    const float* __restrict__ fsr = swSym ? fsB : fsA;
    const float* __restrict__ fsi = swSym ? fsA : fsB;

    const float k = fwr[0];                     // 1/sqrt(33)
    const float invk = 1.0f / k;

    const bool isPair = (tid < PAIRT);
    const bool isV0   = (tid >= PAIRT) && (tid < PAIRT + TPB);
    int ts = 0, j = 0;
    if (isPair)    { ts = tid >> 3; j = tid & 7; }
    else if (isV0) { ts = tid - PAIRT; }
    int tile = blockIdx.x * TPB + ts;
    if (tile >= total_tiles) tile = 0;
    const int n = tile >> 4;                    // ADIM == 16
    const int a = tile & 15;
    const unsigned int rowbase0 = (((unsigned int)n * SDIM) * ADIM + a) * WDIM;

    // ---- Stage 1: coalesced x loads, unfolded T1 to smem ----
    {
        float zr[SDIM], zi[SDIM];               // F_sym[s][t] = z[(s*t)%5]
        #pragma unroll
        for (int q = 0; q < SDIM; q++) { zr[q] = fsr[SDIM + q]; zi[q] = fsi[SDIM + q]; }

        if (isPair) {
            #pragma unroll
            for (int i = 0; i < 4; i++) {
                const int col = j + 8 * i;      // {j, j+8, j+16, j+24}: coalesced
                float xre[SDIM], xim[SDIM];
                #pragma unroll
                for (int t = 0; t < SDIM; t++) {
                    unsigned int idx = rowbase0 + (unsigned int)t * (ADIM * WDIM) + col;
                    if (idx >= xcount) idx = 0;
                    xre[t] = xr[idx];  xim[t] = xi[idx];
                }
                #pragma unroll
                for (int s = 0; s < SDIM; s++) {
                    float Ar = 0.f, Ai = 0.f;
                    #pragma unroll
                    for (int t = 0; t < SDIM; t++) {
                        const int I = (s * t) % SDIM;
                        Ar += zr[I] * xre[t] - zi[I] * xim[t];
                        Ai += zr[I] * xim[t] + zi[I] * xre[t];
                    }
                    sT1[ts][s][col] = make_float2(Ar, Ai);
                }
            }
        } else if (isV0) {                      // column 32
            float xre[SDIM], xim[SDIM];
            #pragma unroll
            for (int t = 0; t < SDIM; t++) {
                unsigned int idx = rowbase0 + (unsigned int)t * (ADIM * WDIM) + 32;
                if (idx >= xcount) idx = 0;
                xre[t] = xr[idx];  xim[t] = xi[idx];
            }
            #pragma unroll
            for (int s = 0; s < SDIM; s++) {
                float Ar = 0.f, Ai = 0.f;
                #pragma unroll
                for (int t = 0; t < SDIM; t++) {
                    const int I = (s * t) % SDIM;
                    Ar += zr[I] * xre[t] - zi[I] * xim[t];
                    Ai += zr[I] * xim[t] + zi[I] * xre[t];
                }
                sT1[ts][s][32] = make_float2(Ar, Ai);
            }
        }
    }
    __syncthreads();

    // ---- Stage 2: fold on read (Ta, Tb), s-split {0,1,2}/{3,4}, E/D to smem ----
    if (isPair) {
        const int c1 = 2 * j + 1, c2 = 2 * j + 2;
        const float2 u1a = make_float2(fwr[WDIM + c1], fwi[WDIM + c1]);
        const float2 u1b = make_float2(fwr[WDIM + c2], fwi[WDIM + c2]);
        const float2 rA = make_float2(u1a.x * invk, u1a.y * invk);
        const float2 rB = make_float2(u1b.x * invk, u1b.y * invk);

        float Ec1[SDIM], Dc1[SDIM], Ec2[SDIM], Dc2[SDIM];
        #pragma unroll
        for (int g = 0; g < 2; g++) {
            const int s0 = g ? 3 : 0;
            const int ns = g ? 2 : 3;
            // cols: [0]=c1 fwd, [1]=c1 mirror, [2]=c2 fwd, [3]=c2 mirror
            float Xr[4][3], Xi[4][3];
            #pragma unroll
            for (int ss = 0; ss < 3; ss++) {
                if (ss < ns) {
                    const float2 t10 = sT1[ts][s0 + ss][0];
                    const float br = k * t10.x, bi = k * t10.y;
                    #pragma unroll
                    for (int c = 0; c < 4; c++) { Xr[c][ss] = br; Xi[c][ss] = bi; }
                }
            }
            float2 fa = u1a, fb = u1b;
            #pragma unroll 4
            for (int w = 1; w <= NPAIR; w++) {
                float2 Ta[3], Tb[3];
                #pragma unroll
                for (int ss = 0; ss < 3; ss++) {
                    if (ss < ns) {
                        Ta[ss] = sT1[ts][s0 + ss][w];
                        Tb[ss] = sT1[ts][s0 + ss][WDIM - w];
                    }
                }
                #pragma unroll
                for (int ss = 0; ss < 3; ss++) {
                    if (ss < ns) {
                        {   // pair c1
                            const float c = fa.x, si = fa.y;
                            const float ur = c  * Ta[ss].x + c  * Tb[ss].x;   // c*Sr
                            const float vr = si * Ta[ss].y - si * Tb[ss].y;   // si*Di
                            const float ui = c  * Ta[ss].y + c  * Tb[ss].y;   // c*Si
                            const float vi = si * Ta[ss].x - si * Tb[ss].x;   // si*Dr
                            Xr[0][ss] += ur - vr;  Xi[0][ss] += ui + vi;
                            Xr[1][ss] += ur + vr;  Xi[1][ss] += ui - vi;
                        }
                        {   // pair c2
                            const float c = fb.x, si = fb.y;
                            const float ur = c  * Ta[ss].x + c  * Tb[ss].x;
                            const float vr = si * Ta[ss].y - si * Tb[ss].y;
                            const float ui = c  * Ta[ss].y + c  * Tb[ss].y;
                            const float vi = si * Ta[ss].x - si * Tb[ss].x;
                            Xr[2][ss] += ur - vr;  Xi[2][ss] += ui + vi;
                            Xr[3][ss] += ur + vr;  Xi[3][ss] += ui - vi;
                        }
                    }
                }
                fa = make_float2(fa.x * rA.x - fa.y * rA.y, fa.x * rA.y + fa.y * rA.x);
                fb = make_float2(fb.x * rB.x - fb.y * rB.y, fb.x * rB.y + fb.y * rB.x);
            }
            #pragma unroll
            for (int ss = 0; ss < 3; ss++) {
                if (ss < ns) {
                    const int s = s0 + ss;
                    const float Pv1 = Xr[0][ss]*Xr[0][ss] + Xi[0][ss]*Xi[0][ss];
                    const float Pm1 = Xr[1][ss]*Xr[1][ss] + Xi[1][ss]*Xi[1][ss];
                    const float Pv2 = Xr[2][ss]*Xr[2][ss] + Xi[2][ss]*Xi[2][ss];
                    const float Pm2 = Xr[3][ss]*Xr[3][ss] + Xi[3][ss]*Xi[3][ss];
                    Ec1[s] = Pv1 + Pm1;  Dc1[s] = Pv1 - Pm1;
                    Ec2[s] = Pv2 + Pm2;  Dc2[s] = Pv2 - Pm2;
                }
            }
        }
        const int i0 = ts * NPAIR + 2 * j;
        sEDa[i0]     = make_float4(Ec1[0], Ec1[1], Ec1[2], Ec1[3]);
        sEDb[i0]     = make_float4(Dc1[0], Dc1[1], Dc1[2], Dc1[3]);
        sEDc[i0]     = make_float2(Ec1[4], Dc1[4]);
        sEDa[i0 + 1] = make_float4(Ec2[0], Ec2[1], Ec2[2], Ec2[3]);
        sEDb[i0 + 1] = make_float4(Dc2[0], Dc2[1], Dc2[2], Dc2[3]);
        sEDc[i0 + 1] = make_float2(Ec2[4], Dc2[4]);
    } else if (isV0) {
        #pragma unroll
        for (int s = 0; s < SDIM; s++) {
            float sr = 0.f, sm = 0.f;
            #pragma unroll 3
            for (int w = 0; w < WDIM; w++) {
                const float2 t1 = sT1[ts][s][w];
                sr += t1.x;  sm += t1.y;
            }
            const float X0r = k * sr, X0i = k * sm;
            sP0[ts][s] = X0r * X0r + X0i * X0i;
        }
    }
    __syncthreads();

    // ---- Stages 3 + 4: verbatim R11 ----
    if (isPair) {
        const int c1 = 2 * j + 1, c2 = 2 * j + 2;
        const float2 u1a = make_float2(fwr[WDIM + c1], fwi[WDIM + c1]);
        const float2 u1b = make_float2(fwr[WDIM + c2], fwi[WDIM + c2]);
        const float2 rA = make_float2(u1a.x * invk, u1a.y * invk);
        const float2 rB = make_float2(u1b.x * invk, u1b.y * invk);

        float zr[SDIM], zi[SDIM];
        #pragma unroll
        for (int q = 0; q < SDIM; q++) { zr[q] = fsr[SDIM + q]; zi[q] = fsi[SDIM + q]; }

        float t2r[2][SDIM], t2i[2][SDIM];
        #pragma unroll
        for (int s = 0; s < SDIM; s++) {
            const float b = k * sP0[ts][s];
            t2r[0][s] = b; t2r[1][s] = b;
            t2i[0][s] = 0.f; t2i[1][s] = 0.f;
        }
        float2 fa = u1a, fb = u1b;
        #pragma unroll 4
        for (int w = 0; w < NPAIR; w++) {
            const float4 E4 = sEDa[ts * NPAIR + w];
            const float4 D4 = sEDb[ts * NPAIR + w];
            const float2 eD = sEDc[ts * NPAIR + w];
            t2r[0][0] += E4.x * fa.x;  t2i[0][0] -= D4.x * fa.y;
            t2r[0][1] += E4.y * fa.x;  t2i[0][1] -= D4.y * fa.y;
            t2r[0][2] += E4.z * fa.x;  t2i[0][2] -= D4.z * fa.y;
            t2r[0][3] += E4.w * fa.x;  t2i[0][3] -= D4.w * fa.y;
            t2r[0][4] += eD.x * fa.x;  t2i[0][4] -= eD.y * fa.y;
            t2r[1][0] += E4.x * fb.x;  t2i[1][0] -= D4.x * fb.y;
            t2r[1][1] += E4.y * fb.x;  t2i[1][1] -= D4.y * fb.y;
            t2r[1][2] += E4.z * fb.x;  t2i[1][2] -= D4.z * fb.y;
            t2r[1][3] += E4.w * fb.x;  t2i[1][3] -= D4.w * fb.y;
            t2r[1][4] += eD.x * fb.x;  t2i[1][4] -= eD.y * fb.y;
            fa = make_float2(fa.x * rA.x - fa.y * rA.y, fa.x * rA.y + fa.y * rA.x);
            fb = make_float2(fb.x * rB.x - fb.y * rB.y, fb.x * rB.y + fb.y * rB.x);
        }
        #pragma unroll
        for (int pc = 0; pc < 2; pc++) {
            const int v = 2 * j + 1 + pc;
            #pragma unroll
            for (int sp = 0; sp < SDIM; sp++) {
                float yr = 0.f, yi = 0.f;
                #pragma unroll
                for (int s = 0; s < SDIM; s++) {
                    const int I = (s * sp) % SDIM;
                    yr += zr[I] * t2r[pc][s] + zi[I] * t2i[pc][s];
                    yi += zr[I] * t2i[pc][s] - zi[I] * t2r[pc][s];
                }
                unsigned int oidx = (((unsigned int)n * SDIM + sp) * ADIM + a) * WDIM + v;
                const int sp2 = (SDIM - sp) % SDIM;
                unsigned int midx = (((unsigned int)n * SDIM + sp2) * ADIM + a) * WDIM + (WDIM - v);
                if (real_only) {
                    if (oidx < out_limit) outf[oidx] = yr;
                    if (midx < out_limit) outf[midx] = yr;
                } else {
                    if (2u * oidx + 1u < out_limit)
                        reinterpret_cast<float2*>(outf)[oidx] = make_float2(yr, yi);
                    if (2u * midx + 1u < out_limit)
                        reinterpret_cast<float2*>(outf)[midx] = make_float2(yr, -yi);
                }
            }
        }
    } else if (isV0) {
        float zr[SDIM], zi[SDIM];
        #pragma unroll
        for (int q = 0; q < SDIM; q++) { zr[q] = fsr[SDIM + q]; zi[q] = fsi[SDIM + q]; }
        float accE[SDIM] = {0,0,0,0,0};
        #pragma unroll 4
        for (int w = 0; w < NPAIR; w++) {
            const float4 E4 = sEDa[ts * NPAIR + w];
            const float2 eD = sEDc[ts * NPAIR + w];
            accE[0] += E4.x; accE[1] += E4.y; accE[2] += E4.z; accE[3] += E4.w;
            accE[4] += eD.x;
        }
        float t2r0[SDIM];
        #pragma unroll
        for (int s = 0; s < SDIM; s++)
            t2r0[s] = k * (sP0[ts][s] + accE[s]);
        #pragma unroll
        for (int sp = 0; sp < SDIM; sp++) {
            float yr = 0.f, yi = 0.f;
            #pragma unroll
            for (int s = 0; s < SDIM; s++) {
                const int I = (s * sp) % SDIM;
                yr += zr[I] * t2r0[s];
                yi -= zi[I] * t2r0[s];
            }
            unsigned int oidx = (((unsigned int)n * SDIM + sp) * ADIM + a) * WDIM;
            if (real_only) {
                if (oidx < out_limit) outf[oidx] = yr;
            } else {
                if (2u * oidx + 1u < out_limit)
                    reinterpret_cast<float2*>(outf)[oidx] = make_float2(yr, yi);
            }
        }
    }
}

extern "C" void kernel_launch(void* const* d_in, const int* in_sizes, int n_in,
                              void* d_out, int out_size)
{
    long long big_raw = -1;
    for (int i = 0; i < n_in; i++)
        if ((long long)in_sizes[i] > big_raw) big_raw = in_sizes[i];

    const float *xr = 0, *xi = 0, *fsA = 0, *fsB = 0, *fwA = 0, *fwB = 0;
    int nsym = 0, nsub = 0, nbig = 0;
    for (int i = 0; i < n_in; i++) {
        const float* p = (const float*)d_in[i];
        long long c = in_sizes[i];
        if (c == SDIM * SDIM) {
            if (nsym++ == 0) fsA = p; else if (!fsB) fsB = p;
        } else if (c == WDIM * WDIM) {
            if (nsub++ == 0) fwA = p; else if (!fwB) fwB = p;
        } else if (c == big_raw) {
            if (nbig++ == 0) xr = p; else if (!xi) xi = p;
        }
    }
    if (!xr || !xi || !fsA || !fsB || !fwA || !fwB) return;

    const long long C = big_raw;
    const int N = (int)(C / (SDIM * ADIM * WDIM));
    const int total_tiles = N * ADIM;
    if (total_tiles <= 0) return;
    const int blocks = (total_tiles + TPB - 1) / TPB;

    const int real_only = ((long long)out_size >= 2 * C) ? 0 : 1;

    autocorr_kernel<<<blocks, THREADS>>>(
        xr, xi, fsA, fsB, fwA, fwB, (float*)d_out, total_tiles,
        (unsigned int)C, (unsigned int)out_size, real_only);
}